// round 2
// baseline (speedup 1.0000x reference)
#include <cuda_runtime.h>

// 23-qubit state: 2 channels x 2^23 floats.
#define NSTATE (1u << 23)

// 64MB ping-pong scratch (device global: allocation-free per harness rules).
__device__ float g_scratch[1u << 24];

// ---------------------------------------------------------------------------
// Kernel A: gates 0,1,2 — contraction over the LOW 7 bits of the index.
// out[m*128+k]        (ch0) = sum_a Ur[k,a]*si[m,a] + Ui[k,a]*sr[m,a]
// out[N + m*128+k]    (ch1) = sum_a Ur[k,a]*sr[m,a] - Ui[k,a]*si[m,a]
// sr = in ch0, si = in ch1.  M = 65536 rows.  64 rows per block, 256 threads.
// SMEM: Ut[2][128][132] (U transposed, padded) + Ssm[2][16][128].
// ---------------------------------------------------------------------------
__global__ void __launch_bounds__(256, 1)
gate_low(const float* __restrict__ in, float* __restrict__ out,
         const float* __restrict__ Ug)
{
    extern __shared__ float sm[];
    float* Ut  = sm;                     // [c][a][132], Ut[c][a][k] = U[c][k*128+a]
    float* Ssm = sm + 2 * 128 * 132;     // [c][16][128]

    const int t = threadIdx.x;

    // Load + transpose U (one-time; 132-pad limits store bank conflicts).
    for (int i = t; i < 2 * 128 * 128; i += 256) {
        const int a = i & 127, k = (i >> 7) & 127, c = i >> 14;
        Ut[c * (128 * 132) + a * 132 + k] = Ug[i];
    }

    const int kg = t & 31;       // 32 k-groups
    const int mg = t >> 5;       // 8 m-groups
    const int k0 = kg << 2;      // 4 consecutive k per thread
    const unsigned rowbase = blockIdx.x * 64u;

    const float* UtR = Ut;
    const float* UtI = Ut + 128 * 132;

    for (int chunk = 0; chunk < 4; ++chunk) {
        __syncthreads();   // Ssm free to overwrite (also covers Ut load on chunk 0)
        const unsigned rb = rowbase + chunk * 16;
        for (int i = t; i < 16 * 128; i += 256) {
            Ssm[i]            = in[rb * 128 + i];
            Ssm[16 * 128 + i] = in[NSTATE + rb * 128 + i];
        }
        __syncthreads();

        const int r0 = mg * 2, r1 = mg * 2 + 1;
        const float* s0r = &Ssm[r0 * 128];
        const float* s0i = &Ssm[16 * 128 + r0 * 128];
        const float* s1r = &Ssm[r1 * 128];
        const float* s1i = &Ssm[16 * 128 + r1 * 128];

        float a00[4] = {0.f, 0.f, 0.f, 0.f};  // row0, ch0
        float a01[4] = {0.f, 0.f, 0.f, 0.f};  // row0, ch1
        float a10[4] = {0.f, 0.f, 0.f, 0.f};  // row1, ch0
        float a11[4] = {0.f, 0.f, 0.f, 0.f};  // row1, ch1

        #pragma unroll 2
        for (int a = 0; a < 128; ++a) {
            const float4 urv = *(const float4*)(UtR + a * 132 + k0);
            const float4 uiv = *(const float4*)(UtI + a * 132 + k0);
            const float ur[4] = {urv.x, urv.y, urv.z, urv.w};
            const float ui[4] = {uiv.x, uiv.y, uiv.z, uiv.w};
            const float sr0 = s0r[a], si0 = s0i[a];
            const float sr1 = s1r[a], si1 = s1i[a];
            #pragma unroll
            for (int j = 0; j < 4; ++j) {
                a00[j] = fmaf(ur[j], si0, a00[j]);
                a00[j] = fmaf(ui[j], sr0, a00[j]);
                a01[j] = fmaf(ur[j], sr0, a01[j]);
                a01[j] = fmaf(-ui[j], si0, a01[j]);
                a10[j] = fmaf(ur[j], si1, a10[j]);
                a10[j] = fmaf(ui[j], sr1, a10[j]);
                a11[j] = fmaf(ur[j], sr1, a11[j]);
                a11[j] = fmaf(-ui[j], si1, a11[j]);
            }
        }

        const unsigned o0 = (rb + r0) * 128u + k0;
        const unsigned o1 = (rb + r1) * 128u + k0;
        *(float4*)(out + o0)          = make_float4(a00[0], a00[1], a00[2], a00[3]);
        *(float4*)(out + NSTATE + o0) = make_float4(a01[0], a01[1], a01[2], a01[3]);
        *(float4*)(out + o1)          = make_float4(a10[0], a10[1], a10[2], a10[3]);
        *(float4*)(out + NSTATE + o1) = make_float4(a11[0], a11[1], a11[2], a11[3]);
    }
}

// ---------------------------------------------------------------------------
// Kernel B: gate 3 — contraction over bits 7..13.
// Per 16384-element chunk (bits 14..22 fixed): s[a][l], a = bits 13..7,
// l = bits 6..0.  out[k][l] = sum_a U[k][a] * s[a][l]  (same cross/real combo).
// One chunk (both channels) per block; 512 blocks, 256 threads.
// SMEM: S0[128][128], S1[128][128], Usm[2][16][128] per k-pass.
// ---------------------------------------------------------------------------
__global__ void __launch_bounds__(256, 1)
gate_high(const float* __restrict__ in, float* __restrict__ out,
          const float* __restrict__ Ug)
{
    extern __shared__ float sm[];
    float* S0  = sm;            // ch0, [a][l]
    float* S1  = sm + 16384;    // ch1
    float* Usm = sm + 32768;    // [c][16][128]

    const int t = threadIdx.x;
    const unsigned cb = blockIdx.x * 16384u;

    for (int i = t; i < 16384; i += 256) {
        S0[i] = in[cb + i];
        S1[i] = in[NSTATE + cb + i];
    }

    const int lg = t & 31;
    const int l0 = lg << 2;     // 4 consecutive l
    const int kg = t >> 5;      // 0..7 -> k = kb+kg and kb+kg+8

    for (int p = 0; p < 8; ++p) {
        __syncthreads();   // prior pass done with Usm (also covers S load on p=0)
        const int kb = p * 16;
        for (int i = t; i < 4096; i += 256) {
            const int a = i & 127, kk = (i >> 7) & 15, c = i >> 11;
            Usm[c * 2048 + kk * 128 + a] = Ug[c * 16384 + (kb + kk) * 128 + a];
        }
        __syncthreads();

        float aA0[4] = {0.f, 0.f, 0.f, 0.f};  // kA, ch0
        float aA1[4] = {0.f, 0.f, 0.f, 0.f};  // kA, ch1
        float aB0[4] = {0.f, 0.f, 0.f, 0.f};  // kB, ch0
        float aB1[4] = {0.f, 0.f, 0.f, 0.f};  // kB, ch1

        const float* UrA = Usm + kg * 128;
        const float* UrB = Usm + (kg + 8) * 128;
        const float* UiA = Usm + 2048 + kg * 128;
        const float* UiB = Usm + 2048 + (kg + 8) * 128;

        #pragma unroll 2
        for (int a = 0; a < 128; ++a) {
            const float4 srv = *(const float4*)(S0 + a * 128 + l0);
            const float4 siv = *(const float4*)(S1 + a * 128 + l0);
            const float sr[4] = {srv.x, srv.y, srv.z, srv.w};
            const float si[4] = {siv.x, siv.y, siv.z, siv.w};
            const float urA = UrA[a], urB = UrB[a];
            const float uiA = UiA[a], uiB = UiB[a];
            #pragma unroll
            for (int j = 0; j < 4; ++j) {
                aA0[j] = fmaf(urA, si[j], aA0[j]);
                aA0[j] = fmaf(uiA, sr[j], aA0[j]);
                aA1[j] = fmaf(urA, sr[j], aA1[j]);
                aA1[j] = fmaf(-uiA, si[j], aA1[j]);
                aB0[j] = fmaf(urB, si[j], aB0[j]);
                aB0[j] = fmaf(uiB, sr[j], aB0[j]);
                aB1[j] = fmaf(urB, sr[j], aB1[j]);
                aB1[j] = fmaf(-uiB, si[j], aB1[j]);
            }
        }

        const unsigned oA = cb + (unsigned)(kb + kg) * 128u + l0;
        const unsigned oB = cb + (unsigned)(kb + kg + 8) * 128u + l0;
        *(float4*)(out + oA)          = make_float4(aA0[0], aA0[1], aA0[2], aA0[3]);
        *(float4*)(out + NSTATE + oA) = make_float4(aA1[0], aA1[1], aA1[2], aA1[3]);
        *(float4*)(out + oB)          = make_float4(aB0[0], aB0[1], aB0[2], aB0[3]);
        *(float4*)(out + NSTATE + oB) = make_float4(aB1[0], aB1[1], aB1[2], aB1[3]);
    }
}

// ---------------------------------------------------------------------------
extern "C" void kernel_launch(void* const* d_in, const int* in_sizes, int n_in,
                              void* d_out, int out_size)
{
    const float* state = (const float*)d_in[0];
    const float* U     = (const float*)d_in[1];
    if (n_in >= 2 && in_sizes[0] < in_sizes[1]) {  // robustness: state is the big one
        const float* tmp = state; state = U; U = tmp;
    }
    float* out = (float*)d_out;

    float* scratch = nullptr;
    cudaGetSymbolAddress((void**)&scratch, g_scratch);

    const size_t smA = (2 * 128 * 132 + 2 * 16 * 128) * sizeof(float);  // 151552
    const size_t smB = (2 * 16384 + 4096) * sizeof(float);              // 147456
    cudaFuncSetAttribute(gate_low,  cudaFuncAttributeMaxDynamicSharedMemorySize, (int)smA);
    cudaFuncSetAttribute(gate_high, cudaFuncAttributeMaxDynamicSharedMemorySize, (int)smB);

    // U layout: [gate][2][128][128] -> gate g at offset g*32768, Ui at +16384.
    gate_low <<<1024, 256, smA>>>(state,   scratch, U);
    gate_low <<<1024, 256, smA>>>(scratch, out,     U + 32768);
    gate_low <<<1024, 256, smA>>>(out,     scratch, U + 2 * 32768);
    gate_high<<< 512, 256, smB>>>(scratch, out,     U + 3 * 32768);
}

// round 4
// speedup vs baseline: 3.3865x; 3.3865x over previous
#include <cuda_runtime.h>
#include <cuda_bf16.h>
#include <cstdint>

#define NSTATE (1u << 23)

// 64MB ping-pong scratch + pre-split/pre-swizzled bf16 U image.
__device__ float g_scratch[1u << 24];
__device__ __nv_bfloat16 g_ubf[262144];   // 4 gates x 4 matrices x 16384 bf16

// SMEM layout (bytes): A tiles 4 x 16384 (64 rows x 256B), B tiles 4 x 32768 (128 x 256B)
#define A_OFF   0u
#define A_TILE  16384u
#define B_OFF   65536u
#define B_TILE  32768u
#define SMEM_BYTES 196608u

#define SGN 0x80008000u

__device__ __forceinline__ uint32_t smem_u32(const void* p) {
    uint32_t a;
    asm("{ .reg .u64 t; cvta.to.shared.u64 t, %1; cvt.u32.u64 %0, t; }" : "=r"(a) : "l"(p));
    return a;
}

#define LDM4(r, addr)                                                           \
    asm volatile("ldmatrix.sync.aligned.m8n8.x4.shared.b16 {%0,%1,%2,%3}, [%4];"\
        : "=r"((r)[0]), "=r"((r)[1]), "=r"((r)[2]), "=r"((r)[3]) : "r"(addr))

#define LDM4T(r, addr)                                                          \
    asm volatile("ldmatrix.sync.aligned.m8n8.x4.trans.shared.b16 {%0,%1,%2,%3}, [%4];"\
        : "=r"((r)[0]), "=r"((r)[1]), "=r"((r)[2]), "=r"((r)[3]) : "r"(addr))

#define MMA(C, A, b0v, b1v)                                                     \
    asm volatile("mma.sync.aligned.m16n8k16.row.col.f32.bf16.bf16.f32 "         \
        "{%0,%1,%2,%3}, {%4,%5,%6,%7}, {%8,%9}, {%0,%1,%2,%3};"                 \
        : "+f"((C)[0]), "+f"((C)[1]), "+f"((C)[2]), "+f"((C)[3])                \
        : "r"((A)[0]), "r"((A)[1]), "r"((A)[2]), "r"((A)[3]), "r"(b0v), "r"(b1v))

// fp32 x8 -> bf16 hi (16B) + bf16 lo (16B)
__device__ __forceinline__ void cvt8(float4 x, float4 y, uint4* hi, uint4* lo) {
    float f[8] = {x.x, x.y, x.z, x.w, y.x, y.y, y.z, y.w};
    uint32_t h[8], l[8];
    #pragma unroll
    for (int i = 0; i < 8; ++i) {
        __nv_bfloat16 hb = __float2bfloat16(f[i]);
        h[i] = (uint32_t)__bfloat16_as_ushort(hb);
        l[i] = (uint32_t)__bfloat16_as_ushort(__float2bfloat16(f[i] - __bfloat162float(hb)));
    }
    *hi = make_uint4(h[0] | (h[1] << 16), h[2] | (h[3] << 16),
                     h[4] | (h[5] << 16), h[6] | (h[7] << 16));
    *lo = make_uint4(l[0] | (l[1] << 16), l[2] | (l[3] << 16),
                     l[4] | (l[5] << 16), l[6] | (l[7] << 16));
}

// ---------------------------------------------------------------------------
// Prep: split U fp32 -> bf16 hi/lo, stored in the exact swizzled SMEM tile
// image (row k, 256B stride, 16B chunk c stored at (c ^ (k&7))).
// Per gate: matrices [Ur_hi, Ur_lo, Ui_hi, Ui_lo], 16384 bf16 each.
__global__ void prep_u(const float* __restrict__ U)
{
    const int i = blockIdx.x * 256 + threadIdx.x;   // 4*2*128*128 = 131072
    const int a = i & 127, k = (i >> 7) & 127, c = (i >> 14) & 1, g = i >> 15;
    const float x = U[i];
    const __nv_bfloat16 hi = __float2bfloat16(x);
    const __nv_bfloat16 lo = __float2bfloat16(x - __bfloat162float(hi));
    const int h = k * 128 + (((a >> 3) ^ (k & 7)) << 3) + (a & 7);
    g_ubf[g * 65536 + (c * 2 + 0) * 16384 + h] = hi;
    g_ubf[g * 65536 + (c * 2 + 1) * 16384 + h] = lo;
}

// ---------------------------------------------------------------------------
// SA=1 (gates 0-2): A = state tile (64 rows m x 128 a), B = U (128 k_out x 128 a).
//   D[m,k] pair: ch0 = Si*Ur + Sr*Ui ; ch1 = Sr*Ur - Si*Ui.
// SA=0 (gate 3): A = U k-half (64 rows k x 128 a), B = S chunk (128 a x 128 l,
//   loaded via ldmatrix.trans). D[k,l]: ch0 = Ur*Si + Ui*Sr ; ch1 = Ur*Sr - Ui*Si.
// Both reduce to the identical MMA pattern with A0..A3 / B0..B3 = (r_hi, r_lo,
// i_hi, i_lo) of the respective operand; the "i*i" product is negated via XOR.
template<int SA>
__global__ void __launch_bounds__(256, 1)
gate_mma(const float* __restrict__ in, float* __restrict__ out,
         const __nv_bfloat16* __restrict__ img)
{
    extern __shared__ char smem[];
    const uint32_t sb = smem_u32(smem);
    const int t = threadIdx.x;
    const int lane = t & 31, w = t >> 5;

    // ---- stage U image (raw copy; already swizzled) ----
    if (SA) {
        const uint4* src = (const uint4*)img;          // 4 x 32KB -> B tiles
        uint4* dst = (uint4*)(smem + B_OFF);
        #pragma unroll
        for (int j = 0; j < 32; ++j) dst[t + 256 * j] = src[t + 256 * j];
    } else {
        const int kh = blockIdx.x & 1;                 // k-half of U rows
        const uint4* src = (const uint4*)img;
        uint4* dst = (uint4*)(smem + A_OFF);
        #pragma unroll
        for (int j = 0; j < 16; ++j) {
            const int idx = t + 256 * j;               // 0..4095
            const int m = idx >> 10, within = idx & 1023;
            dst[idx] = src[m * 2048 + kh * 1024 + within];
        }
    }

    // ---- convert state fp32 -> bf16 hi/lo tiles ----
    if (SA) {
        const size_t base = (size_t)blockIdx.x * 64 * 128;
        #pragma unroll
        for (int s = 0; s < 8; ++s) {
            const int slot = t + 256 * s;              // 0..2047
            const int chunk = slot & 15, r = (slot >> 4) & 63, ch = slot >> 10;
            const float4* p = (const float4*)(in + (size_t)ch * NSTATE + base + r * 128 + chunk * 8);
            uint4 hi, lo;
            cvt8(p[0], p[1], &hi, &lo);
            char* wp = smem + A_OFF + (ch * 2) * A_TILE + r * 256 + ((chunk ^ (r & 7)) * 16);
            *(uint4*)wp = hi;
            *(uint4*)(wp + A_TILE) = lo;
        }
    } else {
        const size_t cb = (size_t)(blockIdx.x >> 1) * 16384;
        #pragma unroll
        for (int s = 0; s < 16; ++s) {
            const int slot = t + 256 * s;              // 0..4095
            const int chunk = slot & 15, a = (slot >> 4) & 127, ch = slot >> 11;
            const float4* p = (const float4*)(in + (size_t)ch * NSTATE + cb + a * 128 + chunk * 8);
            uint4 hi, lo;
            cvt8(p[0], p[1], &hi, &lo);
            char* wp = smem + B_OFF + (ch * 2) * B_TILE + a * 256 + ((chunk ^ (a & 7)) * 16);
            *(uint4*)wp = hi;
            *(uint4*)(wp + B_TILE) = lo;
        }
    }
    __syncthreads();

    // ---- MMA mainloop ----
    const int mrow0 = (w & 3) * 16;          // warp's 16 A-rows
    const int ncol0 = (w >> 2) * 64;         // warp's 64 B-cols

    float acc0[8][4], acc1[8][4];
    #pragma unroll
    for (int j = 0; j < 8; ++j)
        #pragma unroll
        for (int q = 0; q < 4; ++q) { acc0[j][q] = 0.f; acc1[j][q] = 0.f; }

    // A ldmatrix lane addressing (x4: m16 x k16)
    const int ar = mrow0 + (lane & 15);
    const int acl = lane >> 4;               // k-chunk add 0/1
    const uint32_t abase = sb + A_OFF + ar * 256;
    const int ar7 = ar & 7;

    // B ldmatrix lane addressing
    int br_off, bcl;
    if (SA) { br_off = lane & 15;                          bcl = lane >> 4;      }
    else    { br_off = (lane & 7) + ((lane & 16) >> 1);    bcl = (lane >> 3) & 1; }

    #pragma unroll 1
    for (int ks = 0; ks < 8; ++ks) {
        uint32_t af[4][4];
        {
            const int achunk = ks * 2 + acl;
            const uint32_t aa = abase + ((achunk ^ ar7) << 4);
            LDM4(af[0], aa);
            LDM4(af[1], aa + A_TILE);
            LDM4(af[2], aa + 2 * A_TILE);
            LDM4(af[3], aa + 3 * A_TILE);
        }

        #pragma unroll
        for (int g = 0; g < 4; ++g) {
            uint32_t bf[4][4];
            if (SA) {
                const int row = ncol0 + g * 16 + br_off;
                const uint32_t ba = sb + B_OFF + row * 256 + (((ks * 2 + bcl) ^ (row & 7)) << 4);
                LDM4(bf[0], ba);
                LDM4(bf[1], ba + B_TILE);
                LDM4(bf[2], ba + 2 * B_TILE);
                LDM4(bf[3], ba + 3 * B_TILE);
            } else {
                const int row = ks * 16 + br_off;
                const int chunk = ((ncol0 + g * 16) >> 3) + bcl;
                const uint32_t ba = sb + B_OFF + row * 256 + ((chunk ^ (row & 7)) << 4);
                LDM4T(bf[0], ba);
                LDM4T(bf[1], ba + B_TILE);
                LDM4T(bf[2], ba + 2 * B_TILE);
                LDM4T(bf[3], ba + 3 * B_TILE);
            }
            uint32_t nb2[4], nb3[4];
            #pragma unroll
            for (int q = 0; q < 4; ++q) { nb2[q] = bf[2][q] ^ SGN; nb3[q] = bf[3][q] ^ SGN; }

            #pragma unroll
            for (int j2 = 0; j2 < 2; ++j2) {
                const int j = g * 2 + j2;
                // ch1 = A_r * B_r  -  A_i * B_i   (hi*hi + hi*lo + lo*hi each)
                MMA(acc1[j], af[0], bf[0][j2], bf[0][j2 + 2]);
                MMA(acc1[j], af[0], bf[1][j2], bf[1][j2 + 2]);
                MMA(acc1[j], af[1], bf[0][j2], bf[0][j2 + 2]);
                MMA(acc1[j], af[2], nb2[j2],   nb2[j2 + 2]);
                MMA(acc1[j], af[2], nb3[j2],   nb3[j2 + 2]);
                MMA(acc1[j], af[3], nb2[j2],   nb2[j2 + 2]);
                // ch0 = A_i * B_r  +  A_r * B_i
                MMA(acc0[j], af[2], bf[0][j2], bf[0][j2 + 2]);
                MMA(acc0[j], af[2], bf[1][j2], bf[1][j2 + 2]);
                MMA(acc0[j], af[3], bf[0][j2], bf[0][j2 + 2]);
                MMA(acc0[j], af[0], bf[2][j2], bf[2][j2 + 2]);
                MMA(acc0[j], af[0], bf[3][j2], bf[3][j2 + 2]);
                MMA(acc0[j], af[1], bf[2][j2], bf[2][j2 + 2]);
            }
        }
    }

    // ---- epilogue: direct float2 stores ----
    {
        const int rg = lane >> 2, tg = lane & 3;
        const size_t base_row = SA ? (size_t)blockIdx.x * 64
                                   : (size_t)(blockIdx.x >> 1) * 128 + (size_t)(blockIdx.x & 1) * 64;
        const size_t row0 = base_row + mrow0 + rg;
        float* o0 = out;            // ch0 (cross)
        float* o1 = out + NSTATE;   // ch1 (real)
        #pragma unroll
        for (int j = 0; j < 8; ++j) {
            const int n = ncol0 + j * 8 + tg * 2;
            *(float2*)(o0 + row0 * 128 + n)       = make_float2(acc0[j][0], acc0[j][1]);
            *(float2*)(o0 + (row0 + 8) * 128 + n) = make_float2(acc0[j][2], acc0[j][3]);
            *(float2*)(o1 + row0 * 128 + n)       = make_float2(acc1[j][0], acc1[j][1]);
            *(float2*)(o1 + (row0 + 8) * 128 + n) = make_float2(acc1[j][2], acc1[j][3]);
        }
    }
}

// ---------------------------------------------------------------------------
extern "C" void kernel_launch(void* const* d_in, const int* in_sizes, int n_in,
                              void* d_out, int out_size)
{
    const float* state = (const float*)d_in[0];
    const float* U     = (const float*)d_in[1];
    if (n_in >= 2 && in_sizes[0] < in_sizes[1]) {
        const float* tmp = state; state = U; U = tmp;
    }
    float* out = (float*)d_out;

    float* scratch = nullptr;
    cudaGetSymbolAddress((void**)&scratch, g_scratch);
    __nv_bfloat16* ubf = nullptr;
    cudaGetSymbolAddress((void**)&ubf, g_ubf);

    cudaFuncSetAttribute(gate_mma<1>, cudaFuncAttributeMaxDynamicSharedMemorySize, (int)SMEM_BYTES);
    cudaFuncSetAttribute(gate_mma<0>, cudaFuncAttributeMaxDynamicSharedMemorySize, (int)SMEM_BYTES);

    prep_u<<<512, 256>>>(U);
    gate_mma<1><<<1024, 256, SMEM_BYTES>>>(state,   scratch, ubf);            // gate 0
    gate_mma<1><<<1024, 256, SMEM_BYTES>>>(scratch, out,     ubf + 65536);    // gate 1
    gate_mma<1><<<1024, 256, SMEM_BYTES>>>(out,     scratch, ubf + 131072);   // gate 2
    gate_mma<0><<<1024, 256, SMEM_BYTES>>>(scratch, out,     ubf + 196608);   // gate 3
}

// round 5
// speedup vs baseline: 3.5533x; 1.0493x over previous
#include <cuda_runtime.h>
#include <cuda_bf16.h>
#include <cstdint>

#define NSTATE (1u << 23)

// 64MB ping-pong scratch + pre-split/pre-swizzled bf16 U image.
__device__ float g_scratch[1u << 24];
__device__ __nv_bfloat16 g_ubf[262144];   // 4 gates x 4 matrices x 16384 bf16

// SMEM layout (bytes): A tiles 4 x 16384 (64 rows x 256B), B tiles 4 x 32768 (128 x 256B)
#define A_OFF   0u
#define A_TILE  16384u
#define B_OFF   65536u
#define B_TILE  32768u
#define SMEM_BYTES 196608u

#define SGN 0x80008000u

__device__ __forceinline__ uint32_t smem_u32(const void* p) {
    uint32_t a;
    asm("{ .reg .u64 t; cvta.to.shared.u64 t, %1; cvt.u32.u64 %0, t; }" : "=r"(a) : "l"(p));
    return a;
}

#define CPASYNC16(saddr, gptr)                                                  \
    asm volatile("cp.async.cg.shared.global [%0], [%1], 16;"                    \
        :: "r"(saddr), "l"(gptr) : "memory")

#define LDM4(r, addr)                                                           \
    asm volatile("ldmatrix.sync.aligned.m8n8.x4.shared.b16 {%0,%1,%2,%3}, [%4];"\
        : "=r"((r)[0]), "=r"((r)[1]), "=r"((r)[2]), "=r"((r)[3]) : "r"(addr))

#define LDM4T(r, addr)                                                          \
    asm volatile("ldmatrix.sync.aligned.m8n8.x4.trans.shared.b16 {%0,%1,%2,%3}, [%4];"\
        : "=r"((r)[0]), "=r"((r)[1]), "=r"((r)[2]), "=r"((r)[3]) : "r"(addr))

#define MMA(C, A, b0v, b1v)                                                     \
    asm volatile("mma.sync.aligned.m16n8k16.row.col.f32.bf16.bf16.f32 "         \
        "{%0,%1,%2,%3}, {%4,%5,%6,%7}, {%8,%9}, {%0,%1,%2,%3};"                 \
        : "+f"((C)[0]), "+f"((C)[1]), "+f"((C)[2]), "+f"((C)[3])                \
        : "r"((A)[0]), "r"((A)[1]), "r"((A)[2]), "r"((A)[3]), "r"(b0v), "r"(b1v))

// fp32 x8 -> bf16 hi (16B) + bf16 lo (16B)
__device__ __forceinline__ void cvt8(float4 x, float4 y, uint4* hi, uint4* lo) {
    float f[8] = {x.x, x.y, x.z, x.w, y.x, y.y, y.z, y.w};
    uint32_t h[8], l[8];
    #pragma unroll
    for (int i = 0; i < 8; ++i) {
        __nv_bfloat16 hb = __float2bfloat16(f[i]);
        h[i] = (uint32_t)__bfloat16_as_ushort(hb);
        l[i] = (uint32_t)__bfloat16_as_ushort(__float2bfloat16(f[i] - __bfloat162float(hb)));
    }
    *hi = make_uint4(h[0] | (h[1] << 16), h[2] | (h[3] << 16),
                     h[4] | (h[5] << 16), h[6] | (h[7] << 16));
    *lo = make_uint4(l[0] | (l[1] << 16), l[2] | (l[3] << 16),
                     l[4] | (l[5] << 16), l[6] | (l[7] << 16));
}

// ---------------------------------------------------------------------------
// Prep: split U fp32 -> bf16 hi/lo, stored in the exact swizzled SMEM tile
// image (row k, 256B stride, 16B chunk c stored at (c ^ (k&7))).
// Per gate: matrices [Ur_hi, Ur_lo, Ui_hi, Ui_lo], 16384 bf16 each.
__global__ void prep_u(const float* __restrict__ U)
{
    const int i = blockIdx.x * 256 + threadIdx.x;   // 4*2*128*128 = 131072
    const int a = i & 127, k = (i >> 7) & 127, c = (i >> 14) & 1, g = i >> 15;
    const float x = U[i];
    const __nv_bfloat16 hi = __float2bfloat16(x);
    const __nv_bfloat16 lo = __float2bfloat16(x - __bfloat162float(hi));
    const int h = k * 128 + (((a >> 3) ^ (k & 7)) << 3) + (a & 7);
    g_ubf[g * 65536 + (c * 2 + 0) * 16384 + h] = hi;
    g_ubf[g * 65536 + (c * 2 + 1) * 16384 + h] = lo;
}

// ---------------------------------------------------------------------------
// SA=1 (gates 0-2): A = state tile (64 rows m x 128 a), B = U (128 k_out x 128 a).
//   D[m,k] pair: ch0 = Si*Ur + Sr*Ui ; ch1 = Sr*Ur - Si*Ui.
// SA=0 (gate 3): A = U k-half (64 rows k x 128 a), B = S chunk (128 a x 128 l,
//   loaded via ldmatrix.trans). D[k,l]: ch0 = Ur*Si + Ui*Sr ; ch1 = Ur*Sr - Ui*Si.
// Both reduce to the identical MMA pattern with A0..A3 / B0..B3 = (r_hi, r_lo,
// i_hi, i_lo) of the respective operand; the "i*i" product is negated (A-side XOR).
template<int SA>
__global__ void __launch_bounds__(256, 1)
gate_mma(const float* __restrict__ in, float* __restrict__ out,
         const __nv_bfloat16* __restrict__ img)
{
    extern __shared__ char smem[];
    const uint32_t sb = smem_u32(smem);
    const int t = threadIdx.x;
    const int lane = t & 31, w = t >> 5;

    // ---- stage U image via cp.async (overlaps with the convert below) ----
    if (SA) {
        const uint4* src = (const uint4*)img;          // 4 x 32KB -> B tiles
        #pragma unroll
        for (int j = 0; j < 32; ++j) {
            const int idx = t + 256 * j;
            CPASYNC16(sb + B_OFF + idx * 16u, src + idx);
        }
    } else {
        const int kh = blockIdx.x & 1;                 // k-half of U rows
        const uint4* src = (const uint4*)img;
        #pragma unroll
        for (int j = 0; j < 16; ++j) {
            const int idx = t + 256 * j;               // 0..4095
            const int m = idx >> 10, within = idx & 1023;
            CPASYNC16(sb + A_OFF + idx * 16u, src + m * 2048 + kh * 1024 + within);
        }
    }
    asm volatile("cp.async.commit_group;" ::: "memory");

    // ---- convert state fp32 -> bf16 hi/lo tiles (overlapped with cp.async) ----
    if (SA) {
        const size_t base = (size_t)blockIdx.x * 64 * 128;
        #pragma unroll
        for (int s = 0; s < 8; ++s) {
            const int slot = t + 256 * s;              // 0..2047
            const int chunk = slot & 15, r = (slot >> 4) & 63, ch = slot >> 10;
            const float4* p = (const float4*)(in + (size_t)ch * NSTATE + base + r * 128 + chunk * 8);
            uint4 hi, lo;
            cvt8(p[0], p[1], &hi, &lo);
            char* wp = smem + A_OFF + (ch * 2) * A_TILE + r * 256 + ((chunk ^ (r & 7)) * 16);
            *(uint4*)wp = hi;
            *(uint4*)(wp + A_TILE) = lo;
        }
    } else {
        const size_t cb = (size_t)(blockIdx.x >> 1) * 16384;
        #pragma unroll
        for (int s = 0; s < 16; ++s) {
            const int slot = t + 256 * s;              // 0..4095
            const int chunk = slot & 15, a = (slot >> 4) & 127, ch = slot >> 11;
            const float4* p = (const float4*)(in + (size_t)ch * NSTATE + cb + a * 128 + chunk * 8);
            uint4 hi, lo;
            cvt8(p[0], p[1], &hi, &lo);
            char* wp = smem + B_OFF + (ch * 2) * B_TILE + a * 256 + ((chunk ^ (a & 7)) * 16);
            *(uint4*)wp = hi;
            *(uint4*)(wp + B_TILE) = lo;
        }
    }
    asm volatile("cp.async.wait_group 0;" ::: "memory");
    __syncthreads();

    // ---- MMA mainloop ----
    const int mrow0 = (w & 3) * 16;          // warp's 16 A-rows
    const int ncol0 = (w >> 2) * 64;         // warp's 64 B-cols

    float acc0[8][4], acc1[8][4];
    #pragma unroll
    for (int j = 0; j < 8; ++j)
        #pragma unroll
        for (int q = 0; q < 4; ++q) { acc0[j][q] = 0.f; acc1[j][q] = 0.f; }

    // A ldmatrix lane addressing (x4: m16 x k16)
    const int ar = mrow0 + (lane & 15);
    const int acl = lane >> 4;               // k-chunk add 0/1
    const uint32_t abase = sb + A_OFF + ar * 256;
    const int ar7 = ar & 7;

    // B ldmatrix lane addressing
    int br_off, bcl;
    if (SA) { br_off = lane & 15;                          bcl = lane >> 4;      }
    else    { br_off = (lane & 7) + ((lane & 16) >> 1);    bcl = (lane >> 3) & 1; }

    #pragma unroll 1
    for (int ks = 0; ks < 8; ++ks) {
        uint32_t af[4][4], naf2[4], naf3[4];
        {
            const int achunk = ks * 2 + acl;
            const uint32_t aa = abase + ((achunk ^ ar7) << 4);
            LDM4(af[0], aa);
            LDM4(af[1], aa + A_TILE);
            LDM4(af[2], aa + 2 * A_TILE);
            LDM4(af[3], aa + 3 * A_TILE);
        }
        #pragma unroll
        for (int q = 0; q < 4; ++q) { naf2[q] = af[2][q] ^ SGN; naf3[q] = af[3][q] ^ SGN; }

        #pragma unroll
        for (int g = 0; g < 4; ++g) {
            uint32_t bf[4][4];
            if (SA) {
                const int row = ncol0 + g * 16 + br_off;
                const uint32_t ba = sb + B_OFF + row * 256 + (((ks * 2 + bcl) ^ (row & 7)) << 4);
                LDM4(bf[0], ba);
                LDM4(bf[1], ba + B_TILE);
                LDM4(bf[2], ba + 2 * B_TILE);
                LDM4(bf[3], ba + 3 * B_TILE);
            } else {
                const int row = ks * 16 + br_off;
                const int chunk = ((ncol0 + g * 16) >> 3) + bcl;
                const uint32_t ba = sb + B_OFF + row * 256 + ((chunk ^ (row & 7)) << 4);
                LDM4T(bf[0], ba);
                LDM4T(bf[1], ba + B_TILE);
                LDM4T(bf[2], ba + 2 * B_TILE);
                LDM4T(bf[3], ba + 3 * B_TILE);
            }

            #pragma unroll
            for (int j2 = 0; j2 < 2; ++j2) {
                const int j = g * 2 + j2;
                // ch1 = A_r * B_r  -  A_i * B_i   (hi*hi + hi*lo + lo*hi each)
                MMA(acc1[j], af[0], bf[0][j2], bf[0][j2 + 2]);
                MMA(acc1[j], af[0], bf[1][j2], bf[1][j2 + 2]);
                MMA(acc1[j], af[1], bf[0][j2], bf[0][j2 + 2]);
                MMA(acc1[j], naf2,  bf[2][j2], bf[2][j2 + 2]);
                MMA(acc1[j], naf2,  bf[3][j2], bf[3][j2 + 2]);
                MMA(acc1[j], naf3,  bf[2][j2], bf[2][j2 + 2]);
                // ch0 = A_i * B_r  +  A_r * B_i
                MMA(acc0[j], af[2], bf[0][j2], bf[0][j2 + 2]);
                MMA(acc0[j], af[2], bf[1][j2], bf[1][j2 + 2]);
                MMA(acc0[j], af[3], bf[0][j2], bf[0][j2 + 2]);
                MMA(acc0[j], af[0], bf[2][j2], bf[2][j2 + 2]);
                MMA(acc0[j], af[0], bf[3][j2], bf[3][j2 + 2]);
                MMA(acc0[j], af[1], bf[2][j2], bf[2][j2 + 2]);
            }
        }
    }

    // ---- epilogue: direct float2 stores ----
    {
        const int rg = lane >> 2, tg = lane & 3;
        const size_t base_row = SA ? (size_t)blockIdx.x * 64
                                   : (size_t)(blockIdx.x >> 1) * 128 + (size_t)(blockIdx.x & 1) * 64;
        const size_t row0 = base_row + mrow0 + rg;
        float* o0 = out;            // ch0 (cross)
        float* o1 = out + NSTATE;   // ch1 (real)
        #pragma unroll
        for (int j = 0; j < 8; ++j) {
            const int n = ncol0 + j * 8 + tg * 2;
            *(float2*)(o0 + row0 * 128 + n)       = make_float2(acc0[j][0], acc0[j][1]);
            *(float2*)(o0 + (row0 + 8) * 128 + n) = make_float2(acc0[j][2], acc0[j][3]);
            *(float2*)(o1 + row0 * 128 + n)       = make_float2(acc1[j][0], acc1[j][1]);
            *(float2*)(o1 + (row0 + 8) * 128 + n) = make_float2(acc1[j][2], acc1[j][3]);
        }
    }
}

// ---------------------------------------------------------------------------
extern "C" void kernel_launch(void* const* d_in, const int* in_sizes, int n_in,
                              void* d_out, int out_size)
{
    const float* state = (const float*)d_in[0];
    const float* U     = (const float*)d_in[1];
    if (n_in >= 2 && in_sizes[0] < in_sizes[1]) {
        const float* tmp = state; state = U; U = tmp;
    }
    float* out = (float*)d_out;

    float* scratch = nullptr;
    cudaGetSymbolAddress((void**)&scratch, g_scratch);
    __nv_bfloat16* ubf = nullptr;
    cudaGetSymbolAddress((void**)&ubf, g_ubf);

    cudaFuncSetAttribute(gate_mma<1>, cudaFuncAttributeMaxDynamicSharedMemorySize, (int)SMEM_BYTES);
    cudaFuncSetAttribute(gate_mma<0>, cudaFuncAttributeMaxDynamicSharedMemorySize, (int)SMEM_BYTES);

    prep_u<<<512, 256>>>(U);
    gate_mma<1><<<1024, 256, SMEM_BYTES>>>(state,   scratch, ubf);            // gate 0
    gate_mma<1><<<1024, 256, SMEM_BYTES>>>(scratch, out,     ubf + 65536);    // gate 1
    gate_mma<1><<<1024, 256, SMEM_BYTES>>>(out,     scratch, ubf + 131072);   // gate 2
    gate_mma<0><<<1024, 256, SMEM_BYTES>>>(scratch, out,     ubf + 196608);   // gate 3
}

// round 6
// speedup vs baseline: 3.8189x; 1.0747x over previous
#include <cuda_runtime.h>
#include <cuda_bf16.h>
#include <cstdint>

#define NSTATE (1u << 23)

__device__ float g_scratch[1u << 24];
__device__ __nv_bfloat16 g_ubf[262144];   // 4 gates x 4 matrices x 16384 bf16

#define SMEM_BYTES 196608u
#define SGN 0x80008000u

// gates 0-2: U tiles at [0,131072) (4 x 32768), state A buffers at 131072 + buf*32768 (4 x 8192)
#define AL_OFF 131072u
// gate 3: U-half tiles at [0,65536) (4 x 16384), state B buffers at 65536 + buf*65536 (4 x 16384)
#define BH_OFF 65536u

__device__ __forceinline__ uint32_t smem_u32(const void* p) {
    uint32_t a;
    asm("{ .reg .u64 t; cvta.to.shared.u64 t, %1; cvt.u32.u64 %0, t; }" : "=r"(a) : "l"(p));
    return a;
}

#define CPASYNC16(saddr, gptr)                                                  \
    asm volatile("cp.async.cg.shared.global [%0], [%1], 16;"                    \
        :: "r"(saddr), "l"(gptr) : "memory")

#define LDM4(r, addr)                                                           \
    asm volatile("ldmatrix.sync.aligned.m8n8.x4.shared.b16 {%0,%1,%2,%3}, [%4];"\
        : "=r"((r)[0]), "=r"((r)[1]), "=r"((r)[2]), "=r"((r)[3]) : "r"(addr))

#define LDM4T(r, addr)                                                          \
    asm volatile("ldmatrix.sync.aligned.m8n8.x4.trans.shared.b16 {%0,%1,%2,%3}, [%4];"\
        : "=r"((r)[0]), "=r"((r)[1]), "=r"((r)[2]), "=r"((r)[3]) : "r"(addr))

#define MMA(C, A, b0v, b1v)                                                     \
    asm volatile("mma.sync.aligned.m16n8k16.row.col.f32.bf16.bf16.f32 "         \
        "{%0,%1,%2,%3}, {%4,%5,%6,%7}, {%8,%9}, {%0,%1,%2,%3};"                 \
        : "+f"((C)[0]), "+f"((C)[1]), "+f"((C)[2]), "+f"((C)[3])                \
        : "r"((A)[0]), "r"((A)[1]), "r"((A)[2]), "r"((A)[3]), "r"(b0v), "r"(b1v))

// 12-MMA block: ch1 = A_r*B_r - A_i*B_i ; ch0 = A_i*B_r + A_r*B_i (hi*hi+hi*lo+lo*hi each)
#define MMA12(A0, A1, J2)                                                       \
    MMA(acc1[A0], af[0], bf[0][J2], bf[0][(J2) + 2]);                           \
    MMA(acc1[A0], af[0], bf[1][J2], bf[1][(J2) + 2]);                           \
    MMA(acc1[A0], af[1], bf[0][J2], bf[0][(J2) + 2]);                           \
    MMA(acc1[A0], naf2,  bf[2][J2], bf[2][(J2) + 2]);                           \
    MMA(acc1[A0], naf2,  bf[3][J2], bf[3][(J2) + 2]);                           \
    MMA(acc1[A0], naf3,  bf[2][J2], bf[2][(J2) + 2]);                           \
    MMA(acc0[A0], af[2], bf[0][J2], bf[0][(J2) + 2]);                           \
    MMA(acc0[A0], af[2], bf[1][J2], bf[1][(J2) + 2]);                           \
    MMA(acc0[A0], af[3], bf[0][J2], bf[0][(J2) + 2]);                           \
    MMA(acc0[A0], af[0], bf[2][J2], bf[2][(J2) + 2]);                           \
    MMA(acc0[A0], af[0], bf[3][J2], bf[3][(J2) + 2]);                           \
    MMA(acc0[A0], af[1], bf[2][J2], bf[2][(J2) + 2]);

// fp32 x8 -> bf16 hi (16B) + bf16 lo (16B)
__device__ __forceinline__ void cvt8(float4 x, float4 y, uint4* hi, uint4* lo) {
    float f[8] = {x.x, x.y, x.z, x.w, y.x, y.y, y.z, y.w};
    uint32_t h[8], l[8];
    #pragma unroll
    for (int i = 0; i < 8; ++i) {
        __nv_bfloat16 hb = __float2bfloat16(f[i]);
        h[i] = (uint32_t)__bfloat16_as_ushort(hb);
        l[i] = (uint32_t)__bfloat16_as_ushort(__float2bfloat16(f[i] - __bfloat162float(hb)));
    }
    *hi = make_uint4(h[0] | (h[1] << 16), h[2] | (h[3] << 16),
                     h[4] | (h[5] << 16), h[6] | (h[7] << 16));
    *lo = make_uint4(l[0] | (l[1] << 16), l[2] | (l[3] << 16),
                     l[4] | (l[5] << 16), l[6] | (l[7] << 16));
}

// ---------------------------------------------------------------------------
__global__ void prep_u(const float* __restrict__ U)
{
    const int i = blockIdx.x * 256 + threadIdx.x;   // 131072
    const int a = i & 127, k = (i >> 7) & 127, c = (i >> 14) & 1, g = i >> 15;
    const float x = U[i];
    const __nv_bfloat16 hi = __float2bfloat16(x);
    const __nv_bfloat16 lo = __float2bfloat16(x - __bfloat162float(hi));
    const int h = k * 128 + (((a >> 3) ^ (k & 7)) << 3) + (a & 7);
    g_ubf[g * 65536 + (c * 2 + 0) * 16384 + h] = hi;
    g_ubf[g * 65536 + (c * 2 + 1) * 16384 + h] = lo;
}

// ---------------------------------------------------------------------------
// Gates 0-2, persistent: U resident in SMEM; 32-row state chunks double-buffered.
__global__ void __launch_bounds__(256, 1)
gate_lowp(const float* __restrict__ in, float* __restrict__ out,
          const __nv_bfloat16* __restrict__ img)
{
    extern __shared__ char smem[];
    const uint32_t sb = smem_u32(smem);
    const int t = threadIdx.x, lane = t & 31, w = t >> 5;

    // stage U image once (128KB, pre-swizzled)
    {
        const uint4* src = (const uint4*)img;
        #pragma unroll
        for (int j = 0; j < 32; ++j) {
            const int idx = t + 256 * j;
            CPASYNC16(sb + (uint32_t)idx * 16u, src + idx);
        }
        asm volatile("cp.async.commit_group;" ::: "memory");
    }

    int item = blockIdx.x;
    // first chunk convert (direct)
    {
        const size_t base = (size_t)item * 4096;
        #pragma unroll
        for (int s = 0; s < 4; ++s) {
            const int slot = t + 256 * s;
            const int c = slot & 15, r = (slot >> 4) & 31, ch = slot >> 9;
            const float4* p = (const float4*)(in + (size_t)ch * NSTATE + base + r * 128 + c * 8);
            uint4 hi, lo;
            cvt8(p[0], p[1], &hi, &lo);
            char* wp = smem + AL_OFF + (ch * 2) * 8192 + r * 256 + ((c ^ (r & 7)) * 16);
            *(uint4*)wp = hi;
            *(uint4*)(wp + 8192) = lo;
        }
    }
    asm volatile("cp.async.wait_group 0;" ::: "memory");
    __syncthreads();

    const int mrow0 = (w & 1) * 16, ncol0 = (w >> 1) * 32;
    const int ar = mrow0 + (lane & 15), acl = lane >> 4, ar7 = ar & 7;
    const int br_off = lane & 15, bcl = lane >> 4;
    const int rg = lane >> 2, tg = lane & 3;

    uint32_t buf = 0;
    for (; item < 2048; item += 148) {
        const int next = item + 148;
        const bool hasnext = next < 2048;
        float4 stg[8];
        if (hasnext) {
            const size_t base = (size_t)next * 4096;
            #pragma unroll
            for (int s = 0; s < 4; ++s) {
                const int slot = t + 256 * s;
                const int c = slot & 15, r = (slot >> 4) & 31, ch = slot >> 9;
                const float4* p = (const float4*)(in + (size_t)ch * NSTATE + base + r * 128 + c * 8);
                stg[2 * s] = p[0];
                stg[2 * s + 1] = p[1];
            }
        }

        float acc0[4][4], acc1[4][4];
        #pragma unroll
        for (int j = 0; j < 4; ++j)
            #pragma unroll
            for (int q = 0; q < 4; ++q) { acc0[j][q] = 0.f; acc1[j][q] = 0.f; }

        const uint32_t abase = sb + AL_OFF + buf * 32768u + (uint32_t)ar * 256u;
        #pragma unroll 1
        for (int ks = 0; ks < 8; ++ks) {
            uint32_t af[4][4], naf2[4], naf3[4];
            const uint32_t aa = abase + (uint32_t)(((ks * 2 + acl) ^ ar7) << 4);
            LDM4(af[0], aa);
            LDM4(af[1], aa + 8192);
            LDM4(af[2], aa + 16384);
            LDM4(af[3], aa + 24576);
            #pragma unroll
            for (int q = 0; q < 4; ++q) { naf2[q] = af[2][q] ^ SGN; naf3[q] = af[3][q] ^ SGN; }

            #pragma unroll
            for (int g = 0; g < 2; ++g) {
                uint32_t bf[4][4];
                const int row = ncol0 + g * 16 + br_off;
                const uint32_t ba = sb + (uint32_t)row * 256u
                                  + (uint32_t)((((ks * 2 + bcl) ^ (row & 7))) << 4);
                LDM4(bf[0], ba);
                LDM4(bf[1], ba + 32768);
                LDM4(bf[2], ba + 65536);
                LDM4(bf[3], ba + 98304);
                MMA12(g * 2 + 0, _, 0)
                MMA12(g * 2 + 1, _, 1)
            }
        }

        if (hasnext) {
            #pragma unroll
            for (int s = 0; s < 4; ++s) {
                const int slot = t + 256 * s;
                const int c = slot & 15, r = (slot >> 4) & 31, ch = slot >> 9;
                uint4 hi, lo;
                cvt8(stg[2 * s], stg[2 * s + 1], &hi, &lo);
                char* wp = smem + AL_OFF + (buf ^ 1u) * 32768u + (ch * 2) * 8192 + r * 256
                         + ((c ^ (r & 7)) * 16);
                *(uint4*)wp = hi;
                *(uint4*)(wp + 8192) = lo;
            }
        }

        {
            const size_t row0 = (size_t)item * 32 + mrow0 + rg;
            float* o0 = out;
            float* o1 = out + NSTATE;
            #pragma unroll
            for (int j = 0; j < 4; ++j) {
                const int n = ncol0 + j * 8 + tg * 2;
                *(float2*)(o0 + row0 * 128 + n)       = make_float2(acc0[j][0], acc0[j][1]);
                *(float2*)(o0 + (row0 + 8) * 128 + n) = make_float2(acc0[j][2], acc0[j][3]);
                *(float2*)(o1 + row0 * 128 + n)       = make_float2(acc1[j][0], acc1[j][1]);
                *(float2*)(o1 + (row0 + 8) * 128 + n) = make_float2(acc1[j][2], acc1[j][3]);
            }
        }
        __syncthreads();
        buf ^= 1u;
    }
}

// ---------------------------------------------------------------------------
// Gate 3, persistent: A = U k-half resident; B = state (128a x 64l) double-buffered.
__global__ void __launch_bounds__(256, 1)
gate_highp(const float* __restrict__ in, float* __restrict__ out,
           const __nv_bfloat16* __restrict__ img)
{
    extern __shared__ char smem[];
    const uint32_t sb = smem_u32(smem);
    const int t = threadIdx.x, lane = t & 31, w = t >> 5;
    const int khalf = blockIdx.x & 1;
    const int pairid = blockIdx.x >> 1;   // 0..73

    // stage U k-half once (64KB, pre-swizzled; 64 rows per matrix)
    {
        const uint4* src = (const uint4*)img;
        #pragma unroll
        for (int j = 0; j < 16; ++j) {
            const int idx = t + 256 * j;              // 0..4095
            const int m = idx >> 10, within = idx & 1023;
            CPASYNC16(sb + (uint32_t)idx * 16u, src + m * 2048 + khalf * 1024 + within);
        }
        asm volatile("cp.async.commit_group;" ::: "memory");
    }

    int widx = pairid;                    // over 1024 = 512 chunks x 2 l-halves
    // first item convert (direct, 8 slots)
    {
        const int chunk = widx >> 1, lh = widx & 1;
        const size_t cb = (size_t)chunk * 16384;
        #pragma unroll
        for (int s = 0; s < 8; ++s) {
            const int slot = t + 256 * s;
            const int c = slot & 7, a = (slot >> 3) & 127, ch = slot >> 10;
            const float4* p = (const float4*)(in + (size_t)ch * NSTATE + cb + a * 128 + lh * 64 + c * 8);
            uint4 hi, lo;
            cvt8(p[0], p[1], &hi, &lo);
            char* wp = smem + BH_OFF + (ch * 2) * 16384 + a * 128 + ((c ^ (a & 7)) * 16);
            *(uint4*)wp = hi;
            *(uint4*)(wp + 16384) = lo;
        }
    }
    asm volatile("cp.async.wait_group 0;" ::: "memory");
    __syncthreads();

    const int mrow0 = (w & 3) * 16, ncol0 = (w >> 2) * 32;
    const int ar = mrow0 + (lane & 15), acl = lane >> 4, ar7 = ar & 7;
    const int br_off = (lane & 7) + ((lane & 16) >> 1), bcl = (lane >> 3) & 1;
    const int rg = lane >> 2, tg = lane & 3;
    const uint32_t abase = sb + (uint32_t)ar * 256u;

    uint32_t buf = 0;
    for (; widx < 1024; widx += 74) {
        const int chunk = widx >> 1, lh = widx & 1;
        const size_t cb = (size_t)chunk * 16384;
        const int nwidx = widx + 74;
        const bool hasnext = nwidx < 1024;
        const int nchunk = nwidx >> 1, nlh = nwidx & 1;
        const size_t ncb = (size_t)nchunk * 16384;

        float4 stg[8];                    // slots 0..3 staged; 4..7 loaded after MMA
        if (hasnext) {
            #pragma unroll
            for (int s = 0; s < 4; ++s) {
                const int slot = t + 256 * s;
                const int c = slot & 7, a = (slot >> 3) & 127, ch = slot >> 10;
                const float4* p = (const float4*)(in + (size_t)ch * NSTATE + ncb + a * 128 + nlh * 64 + c * 8);
                stg[2 * s] = p[0];
                stg[2 * s + 1] = p[1];
            }
        }

        float acc0[4][4], acc1[4][4];
        #pragma unroll
        for (int j = 0; j < 4; ++j)
            #pragma unroll
            for (int q = 0; q < 4; ++q) { acc0[j][q] = 0.f; acc1[j][q] = 0.f; }

        const uint32_t bbuf = sb + BH_OFF + buf * 65536u;
        #pragma unroll 1
        for (int ks = 0; ks < 8; ++ks) {
            uint32_t af[4][4], naf2[4], naf3[4];
            const uint32_t aa = abase + (uint32_t)(((ks * 2 + acl) ^ ar7) << 4);
            LDM4(af[0], aa);
            LDM4(af[1], aa + 16384);
            LDM4(af[2], aa + 32768);
            LDM4(af[3], aa + 49152);
            #pragma unroll
            for (int q = 0; q < 4; ++q) { naf2[q] = af[2][q] ^ SGN; naf3[q] = af[3][q] ^ SGN; }

            #pragma unroll
            for (int g = 0; g < 2; ++g) {
                uint32_t bf[4][4];
                const int row = ks * 16 + br_off;
                const int cidx = ((ncol0 + g * 16) >> 3) + bcl;
                const uint32_t ba = bbuf + (uint32_t)row * 128u
                                  + (uint32_t)((cidx ^ (row & 7)) << 4);
                LDM4T(bf[0], ba);
                LDM4T(bf[1], ba + 16384);
                LDM4T(bf[2], ba + 32768);
                LDM4T(bf[3], ba + 49152);
                MMA12(g * 2 + 0, _, 0)
                MMA12(g * 2 + 1, _, 1)
            }
        }

        if (hasnext) {
            #pragma unroll
            for (int s = 0; s < 4; ++s) {
                const int slot = t + 256 * s;
                const int c = slot & 7, a = (slot >> 3) & 127, ch = slot >> 10;
                uint4 hi, lo;
                cvt8(stg[2 * s], stg[2 * s + 1], &hi, &lo);
                char* wp = smem + BH_OFF + (buf ^ 1u) * 65536u + (ch * 2) * 16384 + a * 128
                         + ((c ^ (a & 7)) * 16);
                *(uint4*)wp = hi;
                *(uint4*)(wp + 16384) = lo;
            }
            #pragma unroll
            for (int s = 4; s < 8; ++s) {
                const int slot = t + 256 * s;
                const int c = slot & 7, a = (slot >> 3) & 127, ch = slot >> 10;
                const float4* p = (const float4*)(in + (size_t)ch * NSTATE + ncb + a * 128 + nlh * 64 + c * 8);
                uint4 hi, lo;
                cvt8(p[0], p[1], &hi, &lo);
                char* wp = smem + BH_OFF + (buf ^ 1u) * 65536u + (ch * 2) * 16384 + a * 128
                         + ((c ^ (a & 7)) * 16);
                *(uint4*)wp = hi;
                *(uint4*)(wp + 16384) = lo;
            }
        }

        {
            const size_t row0 = (size_t)khalf * 64 + mrow0 + rg;
            float* o0 = out + cb;
            float* o1 = out + NSTATE + cb;
            #pragma unroll
            for (int j = 0; j < 4; ++j) {
                const int n = lh * 64 + ncol0 + j * 8 + tg * 2;
                *(float2*)(o0 + row0 * 128 + n)       = make_float2(acc0[j][0], acc0[j][1]);
                *(float2*)(o0 + (row0 + 8) * 128 + n) = make_float2(acc0[j][2], acc0[j][3]);
                *(float2*)(o1 + row0 * 128 + n)       = make_float2(acc1[j][0], acc1[j][1]);
                *(float2*)(o1 + (row0 + 8) * 128 + n) = make_float2(acc1[j][2], acc1[j][3]);
            }
        }
        __syncthreads();
        buf ^= 1u;
    }
}

// ---------------------------------------------------------------------------
extern "C" void kernel_launch(void* const* d_in, const int* in_sizes, int n_in,
                              void* d_out, int out_size)
{
    const float* state = (const float*)d_in[0];
    const float* U     = (const float*)d_in[1];
    if (n_in >= 2 && in_sizes[0] < in_sizes[1]) {
        const float* tmp = state; state = U; U = tmp;
    }
    float* out = (float*)d_out;

    float* scratch = nullptr;
    cudaGetSymbolAddress((void**)&scratch, g_scratch);
    __nv_bfloat16* ubf = nullptr;
    cudaGetSymbolAddress((void**)&ubf, g_ubf);

    cudaFuncSetAttribute(gate_lowp,  cudaFuncAttributeMaxDynamicSharedMemorySize, (int)SMEM_BYTES);
    cudaFuncSetAttribute(gate_highp, cudaFuncAttributeMaxDynamicSharedMemorySize, (int)SMEM_BYTES);

    prep_u<<<512, 256>>>(U);
    gate_lowp<<<148, 256, SMEM_BYTES>>>(state,   scratch, ubf);            // gate 0
    gate_lowp<<<148, 256, SMEM_BYTES>>>(scratch, out,     ubf + 65536);    // gate 1
    gate_lowp<<<148, 256, SMEM_BYTES>>>(out,     scratch, ubf + 131072);   // gate 2
    gate_highp<<<148, 256, SMEM_BYTES>>>(scratch, out,    ubf + 196608);   // gate 3
}